// round 12
// baseline (speedup 1.0000x reference)
#include <cuda_runtime.h>
#include <cuda_bf16.h>
#include <cstdint>

// MoE router: jitter -> GEMM (16384x4096 @ 4096x64) -> softmax -> biased top-8
// -> L2-norm weights -> bincount.  GEMM via mma.sync.m16n8k16.bf16, 3xBF16
// split.  MT=32, 4 CTAs/SM, KC=32, warp-private A staging (syncwarp only).
// SOFTWARE-PIPELINED B: bh frags for chunk c+1 prefetched into a 2nd register
// buffer during chunk c's MMAs; bl loaded at iter start (covered by T1/T3).
// Near-tie tokens repaired in exact fp32.

#define N_TOK   16384
#define DIM     4096
#define NEXP    64
#define TOPK    8
#define NCAND   12
#define MT      32
#define KC      32
#define NCHUNK  (DIM / KC)      // 128
#define THREADS 128
#define NBLK    (N_TOK / MT)    // 512
#define THRESH  2e-5f

#define OFF_LOGITS 0
#define OFF_SCORES (N_TOK * NEXP)
#define OFF_W      (2 * N_TOK * NEXP)
#define OFF_IDX    (2 * N_TOK * NEXP + N_TOK * TOPK)
#define OFF_CNT    (2 * N_TOK * NEXP + 2 * N_TOK * TOPK)

#define SMEM_BYTES 8448

typedef unsigned long long u64;

// word index within a 128-word warp plane; STS conflict-free, frag LDS <=2-way
#define AWP(kp, tok) ((((kp) * 16) + (tok)) ^ (((kp) & 4) << 2))

// B frags per-lane, linear in global k16-step: [gstep(256)][j(8)][lane] -> uint2
__device__ uint2 g_Bhf[256 * 8 * 32];
__device__ uint2 g_Blf[256 * 8 * 32];
__device__ float g_WT[NEXP * DIM];              // [e][k] fp32 for repair
__device__ int g_nflag;
__device__ int g_list[N_TOK];
__device__ int g_cand[N_TOK * NCAND];

__device__ __forceinline__ uint32_t pack_bf16x2(float hi_elem, float lo_elem) {
    uint32_t d;
    asm("cvt.rn.bf16x2.f32 %0, %1, %2;" : "=r"(d) : "f"(hi_elem), "f"(lo_elem));
    return d;
}

__device__ __forceinline__ void mma_bf16(float* c,
                                         uint32_t a0, uint32_t a1, uint32_t a2, uint32_t a3,
                                         uint32_t b0, uint32_t b1) {
    asm volatile(
        "mma.sync.aligned.m16n8k16.row.col.f32.bf16.bf16.f32 "
        "{%0,%1,%2,%3}, {%4,%5,%6,%7}, {%8,%9}, {%0,%1,%2,%3};"
        : "+f"(c[0]), "+f"(c[1]), "+f"(c[2]), "+f"(c[3])
        : "r"(a0), "r"(a1), "r"(a2), "r"(a3), "r"(b0), "r"(b1));
}

// prep: split W into per-lane bf16 hi/lo frag layout + fp32 transpose; zeroes
// counters/flags.  p = gstep*256 + j*32 + lane, gstep = global k16 step.
__global__ void prep_W_kernel(const float* __restrict__ W, float* __restrict__ cnt) {
    if (blockIdx.x == 0) {
        if (threadIdx.x < NEXP) cnt[threadIdx.x] = 0.0f;
        if (threadIdx.x == 0) g_nflag = 0;
    }
    int p = blockIdx.x * 256 + threadIdx.x;     // 65536
    int lane  = p & 31;
    int j     = (p >> 5) & 7;
    int gstep = p >> 8;                          // 0..255
    int g2  = lane >> 2;
    int tig = lane & 3;
    int e   = j * 8 + g2;
    int k1 = gstep * 16 + 2 * tig;
    int k2 = k1 + 8;
    float w0 = W[(size_t)k1 * NEXP + e];
    float w1 = W[(size_t)(k1 + 1) * NEXP + e];
    float w2 = W[(size_t)k2 * NEXP + e];
    float w3 = W[(size_t)(k2 + 1) * NEXP + e];
    uint32_t h0 = pack_bf16x2(w1, w0);
    uint32_t h1 = pack_bf16x2(w3, w2);
    float r0 = w0 - __uint_as_float(h0 << 16);
    float r1 = w1 - __uint_as_float(h0 & 0xFFFF0000u);
    float r2 = w2 - __uint_as_float(h1 << 16);
    float r3 = w3 - __uint_as_float(h1 & 0xFFFF0000u);
    uint32_t l0 = pack_bf16x2(r1, r0);
    uint32_t l1 = pack_bf16x2(r3, r2);
    g_Bhf[p] = make_uint2(h0, h1);
    g_Blf[p] = make_uint2(l0, l1);
    g_WT[(size_t)e * DIM + k1]     = w0;
    g_WT[(size_t)e * DIM + k1 + 1] = w1;
    g_WT[(size_t)e * DIM + k2]     = w2;
    g_WT[(size_t)e * DIM + k2 + 1] = w3;
}

__global__ void __launch_bounds__(THREADS, 4)
router_kernel(const float* __restrict__ x, const float* __restrict__ sbias_g,
              const float* __restrict__ noise, float* __restrict__ out) {
    extern __shared__ char db[];
    __shared__ float s_bias[NEXP];

    const int tid  = threadIdx.x;
    const int wid  = tid >> 5;
    const int lane = tid & 31;
    const int g    = lane >> 2;
    const int tig  = lane & 3;
    const int set  = wid >> 1;                // which k16 step of each chunk
    const int wTok = (wid & 1) * 16;          // warp token base (m16 tile)
    const int tok0 = blockIdx.x * MT;

    if (tid < NEXP) s_bias[tid] = sbias_g[tid];
    __syncthreads();

    // warp-private staging: lane -> (local token 0..15, k-half of 8 elems)
    const int t_tok  = lane & 15;
    const int t_half = lane >> 4;
    const float* xg = x     + (size_t)(tok0 + wTok + t_tok) * DIM + set * 16 + t_half * 8;
    const float* ng = noise + (size_t)(tok0 + wTok + t_tok) * DIM + set * 16 + t_half * 8;

    uint32_t* const wAh = (uint32_t*)(db + wid * 2048);
    uint32_t* const wAl = (uint32_t*)(db + wid * 2048 + 512);

    // per-lane B pointers (uint2 units); chunk stride = 512 elements
    const uint2* const pBh = g_Bhf + set * 256 + lane;
    const uint2* const pBl = g_Blf + set * 256 + lane;

    float acc[8][4];
#pragma unroll
    for (int j = 0; j < 8; ++j)
#pragma unroll
        for (int q = 0; q < 4; ++q) acc[j][q] = 0.0f;

    float4 rx[2], rn[2];
#pragma unroll
    for (int j = 0; j < 2; ++j) {
        rx[j] = *(const float4*)(xg + 4 * j);
        rn[j] = *(const float4*)(ng + 4 * j);
    }

#define STORE_CHUNK(BUF) do {                                                   \
        uint32_t* Ah = wAh + (BUF) * 256;                                       \
        uint32_t* Al = wAl + (BUF) * 256;                                       \
        _Pragma("unroll")                                                       \
        for (int j = 0; j < 2; ++j) {                                           \
            float v0 = rx[j].x * (0.99f + rn[j].x * 0.02f);                     \
            float v1 = rx[j].y * (0.99f + rn[j].y * 0.02f);                     \
            float v2 = rx[j].z * (0.99f + rn[j].z * 0.02f);                     \
            float v3 = rx[j].w * (0.99f + rn[j].w * 0.02f);                     \
            uint32_t h0 = pack_bf16x2(v1, v0);                                  \
            uint32_t h1 = pack_bf16x2(v3, v2);                                  \
            float r0 = v0 - __uint_as_float(h0 << 16);                          \
            float r1 = v1 - __uint_as_float(h0 & 0xFFFF0000u);                  \
            float r2 = v2 - __uint_as_float(h1 << 16);                          \
            float r3 = v3 - __uint_as_float(h1 & 0xFFFF0000u);                  \
            uint32_t l0 = pack_bf16x2(r1, r0);                                  \
            uint32_t l1 = pack_bf16x2(r3, r2);                                  \
            int kp0 = t_half * 4 + 2 * j;                                       \
            Ah[AWP(kp0, t_tok)]     = h0;                                       \
            Ah[AWP(kp0 + 1, t_tok)] = h1;                                       \
            Al[AWP(kp0, t_tok)]     = l0;                                       \
            Al[AWP(kp0 + 1, t_tok)] = l1;                                       \
        }                                                                       \
    } while (0)

    // one pipelined iteration: chunk C reads A-buf BUF and b-regs BCUR;
    // prefetches bh(C+1) into BNXT, stages A(C+1), loads rx/rn(C+2).
#define ITER(C, BUF, BCUR, BNXT) do {                                           \
        __syncwarp();                                                           \
        const uint32_t* Ah = wAh + (BUF) * 256;                                 \
        const uint32_t* Al = wAl + (BUF) * 256;                                 \
        uint32_t ah[4], al[4];                                                  \
        ah[0] = Ah[AWP(tig, g)];                                                \
        ah[1] = Ah[AWP(tig, g + 8)];                                            \
        ah[2] = Ah[AWP(tig + 4, g)];                                            \
        ah[3] = Ah[AWP(tig + 4, g + 8)];                                        \
        al[0] = Al[AWP(tig, g)];                                                \
        al[1] = Al[AWP(tig, g + 8)];                                            \
        al[2] = Al[AWP(tig + 4, g)];                                            \
        al[3] = Al[AWP(tig + 4, g + 8)];                                        \
        uint2 bl[8];                                                            \
        _Pragma("unroll")                                                       \
        for (int j = 0; j < 8; ++j)                                             \
            bl[j] = __ldg(pBl + (size_t)(C) * 512 + j * 32);                    \
        if ((C) + 1 < NCHUNK) {                                                 \
            _Pragma("unroll")                                                   \
            for (int j = 0; j < 8; ++j)                                         \
                BNXT[j] = __ldg(pBh + (size_t)((C) + 1) * 512 + j * 32);        \
            STORE_CHUNK((BUF) ^ 1);                                             \
        }                                                                       \
        if ((C) + 2 < NCHUNK) {                                                 \
            const int cb = ((C) + 2) * KC;                                      \
            _Pragma("unroll")                                                   \
            for (int j = 0; j < 2; ++j) {                                       \
                rx[j] = *(const float4*)(xg + cb + 4 * j);                      \
                rn[j] = *(const float4*)(ng + cb + 4 * j);                      \
            }                                                                   \
        }                                                                       \
        _Pragma("unroll")                                                       \
        for (int j = 0; j < 8; ++j)                                             \
            mma_bf16(acc[j], ah[0], ah[1], ah[2], ah[3], BCUR[j].x, BCUR[j].y); \
        _Pragma("unroll")                                                       \
        for (int j = 0; j < 8; ++j)                                             \
            mma_bf16(acc[j], al[0], al[1], al[2], al[3], BCUR[j].x, BCUR[j].y); \
        _Pragma("unroll")                                                       \
        for (int j = 0; j < 8; ++j)                                             \
            mma_bf16(acc[j], ah[0], ah[1], ah[2], ah[3], bl[j].x, bl[j].y);     \
    } while (0)

    // prologue: stage A(0); prefetch bh(0); rx/rn <- chunk 1
    STORE_CHUNK(0);
    uint2 bh_a[8], bh_b[8];
#pragma unroll
    for (int j = 0; j < 8; ++j) bh_a[j] = __ldg(pBh + j * 32);
#pragma unroll
    for (int j = 0; j < 2; ++j) {
        rx[j] = *(const float4*)(xg + KC + 4 * j);
        rn[j] = *(const float4*)(ng + KC + 4 * j);
    }

#pragma unroll 1
    for (int c = 0; c < NCHUNK; c += 2) {
        ITER(c,     0, bh_a, bh_b);
        ITER(c + 1, 1, bh_b, bh_a);
    }

    // ---- epilogue: K-set reduction into L[32][65] (overlays staging) ----
    __syncthreads();
    float* L = (float*)db;
    if (set == 0) {
#pragma unroll
        for (int j = 0; j < 8; ++j) {
            int r = wTok + g, cb = j * 8 + tig * 2;
            L[r * 65 + cb]           = acc[j][0];
            L[r * 65 + cb + 1]       = acc[j][1];
            L[(r + 8) * 65 + cb]     = acc[j][2];
            L[(r + 8) * 65 + cb + 1] = acc[j][3];
        }
    }
    __syncthreads();
    if (set == 1) {
#pragma unroll
        for (int j = 0; j < 8; ++j) {
            int r = wTok + g, cb = j * 8 + tig * 2;
            L[r * 65 + cb]           += acc[j][0];
            L[r * 65 + cb + 1]       += acc[j][1];
            L[(r + 8) * 65 + cb]     += acc[j][2];
            L[(r + 8) * 65 + cb + 1] += acc[j][3];
        }
    }
    __syncthreads();

    float* gL = out + OFF_LOGITS + (size_t)tok0 * NEXP;
    for (int idx = tid; idx < MT * NEXP; idx += THREADS)
        gL[idx] = L[(idx >> 6) * 65 + (idx & 63)];
    __syncthreads();

    if (tid < MT) {
        float* row = L + tid * 65;
        float mx = row[0];
#pragma unroll 8
        for (int e = 1; e < NEXP; ++e) mx = fmaxf(mx, row[e]);
        float s = 0.0f;
#pragma unroll 8
        for (int e = 0; e < NEXP; ++e) s += expf(row[e] - mx);
        float inv = 1.0f / s;
#pragma unroll 8
        for (int e = 0; e < NEXP; ++e) row[e] = expf(row[e] - mx) * inv;
    }
    __syncthreads();

    float* gS = out + OFF_SCORES + (size_t)tok0 * NEXP;
    for (int idx = tid; idx < MT * NEXP; idx += THREADS)
        gS[idx] = L[(idx >> 6) * 65 + (idx & 63)];

    // top-12 biased ranking; write top-8; flag near-ties for exact-fp32 repair
    if (tid < MT) {
        const float* rp = L + tid * 65;
        float bv[NCAND];
        int   bix[NCAND];
        u64 mask = 0ull;
#pragma unroll
        for (int k = 0; k < NCAND; ++k) {
            float best = -1e30f;
            int bi = 0;
            for (int e = 0; e < NEXP; ++e) {
                if (!((mask >> e) & 1ull)) {
                    float v = rp[e] + s_bias[e];
                    if (v > best) { best = v; bi = e; }
                }
            }
            mask |= 1ull << bi;
            bv[k] = best;
            bix[k] = bi;
        }
        float w[TOPK], ss = 0.0f;
#pragma unroll
        for (int k = 0; k < TOPK; ++k) { w[k] = rp[bix[k]]; ss += w[k] * w[k]; }
        float winv = 1.0f / sqrtf(ss);

        const int tok = tok0 + tid;
        float* gW = out + OFF_W   + (size_t)tok * TOPK;
        float* gI = out + OFF_IDX + (size_t)tok * TOPK;
#pragma unroll
        for (int k = 0; k < TOPK; ++k) {
            gW[k] = w[k] * winv;
            gI[k] = (float)bix[k];
        }

        float ming = bv[0] - bv[1];
#pragma unroll
        for (int j = 1; j < 8; ++j) ming = fminf(ming, bv[j] - bv[j + 1]);
        if (ming < THRESH) {
            int pos = atomicAdd(&g_nflag, 1);
            g_list[pos] = tok;
#pragma unroll
            for (int j = 0; j < NCAND; ++j) g_cand[tok * NCAND + j] = bix[j];
        }
    }
}

// Repair: recompute 12 candidate logits in exact fp32 for flagged tokens,
// re-rank, rewrite indices + weights (weights gathered from MMA scores row).
__global__ void __launch_bounds__(384, 2)
repair_kernel(const float* __restrict__ x, const float* __restrict__ sbias_g,
              const float* __restrict__ noise, float* __restrict__ out) {
    __shared__ float sxj[DIM];
    __shared__ float sl[NCAND];
    __shared__ int   se[NCAND];

    const int tid  = threadIdx.x;
    const int wid  = tid >> 5;
    const int lane = tid & 31;
    const int n    = g_nflag;

    for (int i = blockIdx.x; i < n; i += gridDim.x) {
        const int tok = g_list[i];
        __syncthreads();

        const float* xr = x     + (size_t)tok * DIM;
        const float* nr = noise + (size_t)tok * DIM;
        for (int idx = tid; idx < DIM; idx += 384)
            sxj[idx] = xr[idx] * (0.99f + nr[idx] * 0.02f);
        __syncthreads();

        if (wid < NCAND) {
            const int e = g_cand[tok * NCAND + wid];
            const float* wt = g_WT + (size_t)e * DIM;
            float a = 0.0f;
            for (int k = lane; k < DIM; k += 32 * 4) {
                a += sxj[k]       * wt[k];
                a += sxj[k + 32]  * wt[k + 32];
                a += sxj[k + 64]  * wt[k + 64];
                a += sxj[k + 96]  * wt[k + 96];
            }
#pragma unroll
            for (int o = 16; o; o >>= 1) a += __shfl_xor_sync(0xFFFFFFFFu, a, o);
            if (lane == 0) { sl[wid] = a; se[wid] = e; }
        }
        __syncthreads();

        if (tid == 0) {
            float mxl = sl[0];
#pragma unroll
            for (int j = 1; j < NCAND; ++j) mxl = fmaxf(mxl, sl[j]);
            float s0 = out[OFF_SCORES + (size_t)tok * NEXP + se[0]];
            float C = s0 / expf(sl[0] - mxl);
            float bval[NCAND];
#pragma unroll
            for (int j = 0; j < NCAND; ++j)
                bval[j] = expf(sl[j] - mxl) * C + sbias_g[se[j]];

            int ix[TOPK];
            unsigned m2 = 0;
#pragma unroll
            for (int k = 0; k < TOPK; ++k) {
                float best = -1e30f;
                int bj = 0, beste = NEXP;
                for (int j = 0; j < NCAND; ++j) {
                    if (!((m2 >> j) & 1u)) {
                        float v = bval[j];
                        int e = se[j];
                        if (v > best || (v == best && e < beste)) {
                            best = v; bj = j; beste = e;
                        }
                    }
                }
                m2 |= 1u << bj;
                ix[k] = se[bj];
            }
            float w[TOPK], ss = 0.0f;
#pragma unroll
            for (int k = 0; k < TOPK; ++k) {
                w[k] = out[OFF_SCORES + (size_t)tok * NEXP + ix[k]];
                ss += w[k] * w[k];
            }
            float winv = 1.0f / sqrtf(ss);
            float* gW = out + OFF_W   + (size_t)tok * TOPK;
            float* gI = out + OFF_IDX + (size_t)tok * TOPK;
#pragma unroll
            for (int k = 0; k < TOPK; ++k) {
                gW[k] = w[k] * winv;
                gI[k] = (float)ix[k];
            }
        }
    }
}

__global__ void bincount_kernel(const float* __restrict__ gI, float* __restrict__ cnt) {
    __shared__ int h[NEXP];
    const int tid = threadIdx.x;
    if (tid < NEXP) h[tid] = 0;
    __syncthreads();
    for (int idx = blockIdx.x * blockDim.x + tid; idx < N_TOK * TOPK;
         idx += gridDim.x * blockDim.x)
        atomicAdd(&h[(int)gI[idx]], 1);
    __syncthreads();
    if (tid < NEXP && h[tid]) atomicAdd(&cnt[tid], (float)h[tid]);
}

extern "C" void kernel_launch(void* const* d_in, const int* in_sizes, int n_in,
                              void* d_out, int out_size) {
    const float* x     = (const float*)d_in[0];
    const float* W     = (const float*)d_in[1];
    const float* sbias = (const float*)d_in[2];
    const float* noise = (const float*)d_in[3];
    float* out = (float*)d_out;

    prep_W_kernel<<<256, 256>>>(W, out + OFF_CNT);
    router_kernel<<<NBLK, THREADS, SMEM_BYTES>>>(x, sbias, noise, out);
    repair_kernel<<<1024, 384>>>(x, sbias, noise, out);
    bincount_kernel<<<256, 256>>>(out + OFF_IDX, out + OFF_CNT);
}

// round 13
// speedup vs baseline: 1.1253x; 1.1253x over previous
#include <cuda_runtime.h>
#include <cuda_bf16.h>
#include <cstdint>

// MoE router: jitter -> GEMM (16384x4096 @ 4096x64) -> softmax -> biased top-8
// -> L2-norm weights -> bincount.  GEMM via mma.sync.m16n8k16.bf16, 3xBF16
// split.  MT=16, 8 CTAs/SM (grid 1024, 64 thr = 2 warps: 16-token tile x
// 2 K-sets).  Same per-SM work as the 234us champion but 8 independent CTAs
// interleave per SM and barriers span only 2 warps.  B frags from L2.
// Near-tie tokens repaired in exact fp32.

#define N_TOK   16384
#define DIM     4096
#define NEXP    64
#define TOPK    8
#define NCAND   12
#define MT      16
#define KC      32              // K per chunk = 16 kp words = 2 k16-steps
#define NCHUNK  (DIM / KC)      // 128
#define THREADS 64
#define NBLK    (N_TOK / MT)    // 1024
#define THRESH  2e-5f

#define OFF_LOGITS 0
#define OFF_SCORES (N_TOK * NEXP)
#define OFF_W      (2 * N_TOK * NEXP)
#define OFF_IDX    (2 * N_TOK * NEXP + N_TOK * TOPK)
#define OFF_CNT    (2 * N_TOK * NEXP + 2 * N_TOK * TOPK)

// dynamic smem: A planes, double buffered. per buf: hi 1KB + lo 1KB.
// Epilogue L[16][65] (4160B) overlays.
#define AHIB(b) ((b) * 2048)
#define ALOB(b) ((b) * 2048 + 1024)
#define SMEM_BYTES 4480

typedef unsigned long long u64;

// word index within a 256-word A plane (16 kp x 16 tok).
// XOR bit4 when kp&4: STS conflict-free (verified), frag LDS <=2-way.
#define AW(kp, tok) ((((kp) * 16) + (tok)) ^ (((kp) & 4) << 2))

// B frags per-lane, linear in global k16-step: [gstep(256)][j(8)][lane] -> uint2
__device__ uint2 g_Bhf[256 * 8 * 32];
__device__ uint2 g_Blf[256 * 8 * 32];
__device__ float g_WT[NEXP * DIM];              // [e][k] fp32 for repair
__device__ int g_nflag;
__device__ int g_list[N_TOK];
__device__ int g_cand[N_TOK * NCAND];

__device__ __forceinline__ uint32_t pack_bf16x2(float hi_elem, float lo_elem) {
    uint32_t d;
    asm("cvt.rn.bf16x2.f32 %0, %1, %2;" : "=r"(d) : "f"(hi_elem), "f"(lo_elem));
    return d;
}

__device__ __forceinline__ void mma_bf16(float* c,
                                         uint32_t a0, uint32_t a1, uint32_t a2, uint32_t a3,
                                         uint32_t b0, uint32_t b1) {
    asm volatile(
        "mma.sync.aligned.m16n8k16.row.col.f32.bf16.bf16.f32 "
        "{%0,%1,%2,%3}, {%4,%5,%6,%7}, {%8,%9}, {%0,%1,%2,%3};"
        : "+f"(c[0]), "+f"(c[1]), "+f"(c[2]), "+f"(c[3])
        : "r"(a0), "r"(a1), "r"(a2), "r"(a3), "r"(b0), "r"(b1));
}

// prep: split W into per-lane bf16 hi/lo frag layout + fp32 transpose; zeroes
// counters/flags.  p = gstep*256 + j*32 + lane, gstep = global k16 step.
__global__ void prep_W_kernel(const float* __restrict__ W, float* __restrict__ cnt) {
    if (blockIdx.x == 0) {
        if (threadIdx.x < NEXP) cnt[threadIdx.x] = 0.0f;
        if (threadIdx.x == 0) g_nflag = 0;
    }
    int p = blockIdx.x * 256 + threadIdx.x;     // 65536
    int lane  = p & 31;
    int j     = (p >> 5) & 7;
    int gstep = p >> 8;                          // 0..255
    int g2  = lane >> 2;
    int tig = lane & 3;
    int e   = j * 8 + g2;
    int k1 = gstep * 16 + 2 * tig;
    int k2 = k1 + 8;
    float w0 = W[(size_t)k1 * NEXP + e];
    float w1 = W[(size_t)(k1 + 1) * NEXP + e];
    float w2 = W[(size_t)k2 * NEXP + e];
    float w3 = W[(size_t)(k2 + 1) * NEXP + e];
    uint32_t h0 = pack_bf16x2(w1, w0);
    uint32_t h1 = pack_bf16x2(w3, w2);
    float r0 = w0 - __uint_as_float(h0 << 16);
    float r1 = w1 - __uint_as_float(h0 & 0xFFFF0000u);
    float r2 = w2 - __uint_as_float(h1 << 16);
    float r3 = w3 - __uint_as_float(h1 & 0xFFFF0000u);
    uint32_t l0 = pack_bf16x2(r1, r0);
    uint32_t l1 = pack_bf16x2(r3, r2);
    g_Bhf[p] = make_uint2(h0, h1);
    g_Blf[p] = make_uint2(l0, l1);
    g_WT[(size_t)e * DIM + k1]     = w0;
    g_WT[(size_t)e * DIM + k1 + 1] = w1;
    g_WT[(size_t)e * DIM + k2]     = w2;
    g_WT[(size_t)e * DIM + k2 + 1] = w3;
}

__global__ void __launch_bounds__(THREADS, 8)
router_kernel(const float* __restrict__ x, const float* __restrict__ sbias_g,
              const float* __restrict__ noise, float* __restrict__ out) {
    extern __shared__ char db[];
    __shared__ float s_bias[NEXP];

    const int tid  = threadIdx.x;
    const int wid  = tid >> 5;                // 0..1
    const int lane = tid & 31;
    const int g    = lane >> 2;
    const int tig  = lane & 3;
    const int set  = wid;                     // K-set: which k16 step of chunk
    const int tok0 = blockIdx.x * MT;

    s_bias[tid] = sbias_g[tid];               // THREADS == NEXP == 64

    // staging: thread -> (token 0..15, k-quarter of 8 elems = 4 kp)
    const int t_tok = tid & 15;
    const int t_q   = tid >> 4;               // 0..3
    const float* xg = x     + (size_t)(tok0 + t_tok) * DIM + t_q * 8;
    const float* ng = noise + (size_t)(tok0 + t_tok) * DIM + t_q * 8;

    float acc[8][4];
#pragma unroll
    for (int j = 0; j < 8; ++j)
#pragma unroll
        for (int q = 0; q < 4; ++q) acc[j][q] = 0.0f;

    float4 rx[2], rn[2];
#pragma unroll
    for (int j = 0; j < 2; ++j) {
        rx[j] = *(const float4*)(xg + 4 * j);
        rn[j] = *(const float4*)(ng + 4 * j);
    }

#define STORE_CHUNK(BUF) do {                                                   \
        uint32_t* Ah = (uint32_t*)(db + AHIB(BUF));                             \
        uint32_t* Al = (uint32_t*)(db + ALOB(BUF));                             \
        _Pragma("unroll")                                                       \
        for (int j = 0; j < 2; ++j) {                                           \
            float v0 = rx[j].x * (0.99f + rn[j].x * 0.02f);                     \
            float v1 = rx[j].y * (0.99f + rn[j].y * 0.02f);                     \
            float v2 = rx[j].z * (0.99f + rn[j].z * 0.02f);                     \
            float v3 = rx[j].w * (0.99f + rn[j].w * 0.02f);                     \
            uint32_t h0 = pack_bf16x2(v1, v0);                                  \
            uint32_t h1 = pack_bf16x2(v3, v2);                                  \
            float r0 = v0 - __uint_as_float(h0 << 16);                          \
            float r1 = v1 - __uint_as_float(h0 & 0xFFFF0000u);                  \
            float r2 = v2 - __uint_as_float(h1 << 16);                          \
            float r3 = v3 - __uint_as_float(h1 & 0xFFFF0000u);                  \
            uint32_t l0 = pack_bf16x2(r1, r0);                                  \
            uint32_t l1 = pack_bf16x2(r3, r2);                                  \
            int kp0 = t_q * 4 + 2 * j;                                          \
            Ah[AW(kp0, t_tok)]     = h0;                                        \
            Ah[AW(kp0 + 1, t_tok)] = h1;                                        \
            Al[AW(kp0, t_tok)]     = l0;                                        \
            Al[AW(kp0 + 1, t_tok)] = l1;                                        \
        }                                                                       \
    } while (0)

    STORE_CHUNK(0);
    __syncthreads();

#pragma unroll 1
    for (int c = 0; c < NCHUNK; ++c) {
        const int buf = c & 1;
        const bool more = (c + 1 < NCHUNK);

        if (more) {
            const int cb = (c + 1) * KC;
#pragma unroll
            for (int j = 0; j < 2; ++j) {
                rx[j] = *(const float4*)(xg + cb + 4 * j);
                rn[j] = *(const float4*)(ng + cb + 4 * j);
            }
        }

        // ---- my k16 step: B frags from L2, A frags from smem ----
        {
            const size_t gstep = (size_t)c * 2 + set;
            const uint2* Bh = g_Bhf + gstep * 256 + lane;
            const uint2* Bl = g_Blf + gstep * 256 + lane;
            uint2 b[8];
#pragma unroll
            for (int j = 0; j < 8; ++j) b[j] = __ldg(Bh + j * 32);

            const uint32_t* Ah = (const uint32_t*)(db + AHIB(buf));
            const uint32_t* Al = (const uint32_t*)(db + ALOB(buf));
            const int kb = set * 8;
            uint32_t ah[4], al[4];
            ah[0] = Ah[AW(kb + tig, g)];
            ah[1] = Ah[AW(kb + tig, g + 8)];
            ah[2] = Ah[AW(kb + tig + 4, g)];
            ah[3] = Ah[AW(kb + tig + 4, g + 8)];
            al[0] = Al[AW(kb + tig, g)];
            al[1] = Al[AW(kb + tig, g + 8)];
            al[2] = Al[AW(kb + tig + 4, g)];
            al[3] = Al[AW(kb + tig + 4, g + 8)];

            // T1: a_hi * b_hi
#pragma unroll
            for (int j = 0; j < 8; ++j)
                mma_bf16(acc[j], ah[0], ah[1], ah[2], ah[3], b[j].x, b[j].y);
            // T3: a_lo * b_hi
#pragma unroll
            for (int j = 0; j < 8; ++j)
                mma_bf16(acc[j], al[0], al[1], al[2], al[3], b[j].x, b[j].y);
            // T2: a_hi * b_lo (reuse b regs)
#pragma unroll
            for (int j = 0; j < 8; ++j) b[j] = __ldg(Bl + j * 32);
#pragma unroll
            for (int j = 0; j < 8; ++j)
                mma_bf16(acc[j], ah[0], ah[1], ah[2], ah[3], b[j].x, b[j].y);
        }

        // store chunk c+1 into buf^1 (disjoint from buf; prior readers of
        // buf^1 were fenced by chunk c-1's barrier)
        if (more) STORE_CHUNK(buf ^ 1);
        __syncthreads();
    }

    // ---- epilogue: K-set reduction into L[16][65] (overlays staging) ----
    float* L = (float*)db;
    if (set == 0) {
#pragma unroll
        for (int j = 0; j < 8; ++j) {
            int r = g, cb = j * 8 + tig * 2;
            L[r * 65 + cb]           = acc[j][0];
            L[r * 65 + cb + 1]       = acc[j][1];
            L[(r + 8) * 65 + cb]     = acc[j][2];
            L[(r + 8) * 65 + cb + 1] = acc[j][3];
        }
    }
    __syncthreads();
    if (set == 1) {
#pragma unroll
        for (int j = 0; j < 8; ++j) {
            int r = g, cb = j * 8 + tig * 2;
            L[r * 65 + cb]           += acc[j][0];
            L[r * 65 + cb + 1]       += acc[j][1];
            L[(r + 8) * 65 + cb]     += acc[j][2];
            L[(r + 8) * 65 + cb + 1] += acc[j][3];
        }
    }
    __syncthreads();

    float* gL = out + OFF_LOGITS + (size_t)tok0 * NEXP;
    for (int idx = tid; idx < MT * NEXP; idx += THREADS)
        gL[idx] = L[(idx >> 6) * 65 + (idx & 63)];
    __syncthreads();

    if (tid < MT) {
        float* row = L + tid * 65;
        float mx = row[0];
#pragma unroll 8
        for (int e = 1; e < NEXP; ++e) mx = fmaxf(mx, row[e]);
        float s = 0.0f;
#pragma unroll 8
        for (int e = 0; e < NEXP; ++e) s += expf(row[e] - mx);
        float inv = 1.0f / s;
#pragma unroll 8
        for (int e = 0; e < NEXP; ++e) row[e] = expf(row[e] - mx) * inv;
    }
    __syncthreads();

    float* gS = out + OFF_SCORES + (size_t)tok0 * NEXP;
    for (int idx = tid; idx < MT * NEXP; idx += THREADS)
        gS[idx] = L[(idx >> 6) * 65 + (idx & 63)];

    // top-12 biased ranking; write top-8; flag near-ties for exact-fp32 repair
    if (tid < MT) {
        const float* rp = L + tid * 65;
        float bv[NCAND];
        int   bix[NCAND];
        u64 mask = 0ull;
#pragma unroll
        for (int k = 0; k < NCAND; ++k) {
            float best = -1e30f;
            int bi = 0;
            for (int e = 0; e < NEXP; ++e) {
                if (!((mask >> e) & 1ull)) {
                    float v = rp[e] + s_bias[e];
                    if (v > best) { best = v; bi = e; }
                }
            }
            mask |= 1ull << bi;
            bv[k] = best;
            bix[k] = bi;
        }
        float w[TOPK], ss = 0.0f;
#pragma unroll
        for (int k = 0; k < TOPK; ++k) { w[k] = rp[bix[k]]; ss += w[k] * w[k]; }
        float winv = 1.0f / sqrtf(ss);

        const int tok = tok0 + tid;
        float* gW = out + OFF_W   + (size_t)tok * TOPK;
        float* gI = out + OFF_IDX + (size_t)tok * TOPK;
#pragma unroll
        for (int k = 0; k < TOPK; ++k) {
            gW[k] = w[k] * winv;
            gI[k] = (float)bix[k];
        }

        float ming = bv[0] - bv[1];
#pragma unroll
        for (int j = 1; j < 8; ++j) ming = fminf(ming, bv[j] - bv[j + 1]);
        if (ming < THRESH) {
            int pos = atomicAdd(&g_nflag, 1);
            g_list[pos] = tok;
#pragma unroll
            for (int j = 0; j < NCAND; ++j) g_cand[tok * NCAND + j] = bix[j];
        }
    }
}

// Repair: recompute 12 candidate logits in exact fp32 for flagged tokens,
// re-rank, rewrite indices + weights (weights gathered from MMA scores row).
__global__ void __launch_bounds__(384, 2)
repair_kernel(const float* __restrict__ x, const float* __restrict__ sbias_g,
              const float* __restrict__ noise, float* __restrict__ out) {
    __shared__ float sxj[DIM];
    __shared__ float sl[NCAND];
    __shared__ int   se[NCAND];

    const int tid  = threadIdx.x;
    const int wid  = tid >> 5;
    const int lane = tid & 31;
    const int n    = g_nflag;

    for (int i = blockIdx.x; i < n; i += gridDim.x) {
        const int tok = g_list[i];
        __syncthreads();

        const float* xr = x     + (size_t)tok * DIM;
        const float* nr = noise + (size_t)tok * DIM;
        for (int idx = tid; idx < DIM; idx += 384)
            sxj[idx] = xr[idx] * (0.99f + nr[idx] * 0.02f);
        __syncthreads();

        if (wid < NCAND) {
            const int e = g_cand[tok * NCAND + wid];
            const float* wt = g_WT + (size_t)e * DIM;
            float a = 0.0f;
            for (int k = lane; k < DIM; k += 32 * 4) {
                a += sxj[k]       * wt[k];
                a += sxj[k + 32]  * wt[k + 32];
                a += sxj[k + 64]  * wt[k + 64];
                a += sxj[k + 96]  * wt[k + 96];
            }
#pragma unroll
            for (int o = 16; o; o >>= 1) a += __shfl_xor_sync(0xFFFFFFFFu, a, o);
            if (lane == 0) { sl[wid] = a; se[wid] = e; }
        }
        __syncthreads();

        if (tid == 0) {
            float mxl = sl[0];
#pragma unroll
            for (int j = 1; j < NCAND; ++j) mxl = fmaxf(mxl, sl[j]);
            float s0 = out[OFF_SCORES + (size_t)tok * NEXP + se[0]];
            float C = s0 / expf(sl[0] - mxl);
            float bval[NCAND];
#pragma unroll
            for (int j = 0; j < NCAND; ++j)
                bval[j] = expf(sl[j] - mxl) * C + sbias_g[se[j]];

            int ix[TOPK];
            unsigned m2 = 0;
#pragma unroll
            for (int k = 0; k < TOPK; ++k) {
                float best = -1e30f;
                int bj = 0, beste = NEXP;
                for (int j = 0; j < NCAND; ++j) {
                    if (!((m2 >> j) & 1u)) {
                        float v = bval[j];
                        int e = se[j];
                        if (v > best || (v == best && e < beste)) {
                            best = v; bj = j; beste = e;
                        }
                    }
                }
                m2 |= 1u << bj;
                ix[k] = se[bj];
            }
            float w[TOPK], ss = 0.0f;
#pragma unroll
            for (int k = 0; k < TOPK; ++k) {
                w[k] = out[OFF_SCORES + (size_t)tok * NEXP + ix[k]];
                ss += w[k] * w[k];
            }
            float winv = 1.0f / sqrtf(ss);
            float* gW = out + OFF_W   + (size_t)tok * TOPK;
            float* gI = out + OFF_IDX + (size_t)tok * TOPK;
#pragma unroll
            for (int k = 0; k < TOPK; ++k) {
                gW[k] = w[k] * winv;
                gI[k] = (float)ix[k];
            }
        }
    }
}

__global__ void bincount_kernel(const float* __restrict__ gI, float* __restrict__ cnt) {
    __shared__ int h[NEXP];
    const int tid = threadIdx.x;
    if (tid < NEXP) h[tid] = 0;
    __syncthreads();
    for (int idx = blockIdx.x * blockDim.x + tid; idx < N_TOK * TOPK;
         idx += gridDim.x * blockDim.x)
        atomicAdd(&h[(int)gI[idx]], 1);
    __syncthreads();
    if (tid < NEXP && h[tid]) atomicAdd(&cnt[tid], (float)h[tid]);
}

extern "C" void kernel_launch(void* const* d_in, const int* in_sizes, int n_in,
                              void* d_out, int out_size) {
    const float* x     = (const float*)d_in[0];
    const float* W     = (const float*)d_in[1];
    const float* sbias = (const float*)d_in[2];
    const float* noise = (const float*)d_in[3];
    float* out = (float*)d_out;

    prep_W_kernel<<<256, 256>>>(W, out + OFF_CNT);
    router_kernel<<<NBLK, THREADS, SMEM_BYTES>>>(x, sbias, noise, out);
    repair_kernel<<<1024, 384>>>(x, sbias, noise, out);
    bincount_kernel<<<256, 256>>>(out + OFF_IDX, out + OFF_CNT);
}

// round 14
// speedup vs baseline: 1.1739x; 1.0432x over previous
#include <cuda_runtime.h>
#include <cuda_fp16.h>
#include <cstdint>

// MoE router: jitter -> GEMM (16384x4096 @ 4096x64) -> softmax -> biased top-8
// -> L2-norm weights -> bincount.  GEMM via mma.sync.m16n8k16.f16 (f32 accum),
// 3xFP16 split: hi+lo = 22 mantissa bits -> logit noise ~1e-6 -> THRESH=1e-6
// -> ~20x fewer repair flags.  MT=16, 8 CTAs/SM (grid 1024, 64 thr).
// B frags from L2.  Near-tie tokens repaired in exact fp32.

#define N_TOK   16384
#define DIM     4096
#define NEXP    64
#define TOPK    8
#define NCAND   12
#define MT      16
#define KC      32              // K per chunk = 16 kp words = 2 k16-steps
#define NCHUNK  (DIM / KC)      // 128
#define THREADS 64
#define NBLK    (N_TOK / MT)    // 1024
#define THRESH  1e-6f

#define OFF_LOGITS 0
#define OFF_SCORES (N_TOK * NEXP)
#define OFF_W      (2 * N_TOK * NEXP)
#define OFF_IDX    (2 * N_TOK * NEXP + N_TOK * TOPK)
#define OFF_CNT    (2 * N_TOK * NEXP + 2 * N_TOK * TOPK)

// dynamic smem: A planes, double buffered. per buf: hi 1KB + lo 1KB.
// Epilogue L[16][65] (4160B) overlays.
#define AHIB(b) ((b) * 2048)
#define ALOB(b) ((b) * 2048 + 1024)
#define SMEM_BYTES 4480

typedef unsigned long long u64;

// word index within a 256-word A plane (16 kp x 16 tok).
// XOR bit4 when kp&4: STS conflict-free, frag LDS <=2-way.
#define AW(kp, tok) ((((kp) * 16) + (tok)) ^ (((kp) & 4) << 2))

// B frags per-lane, linear in global k16-step: [gstep(256)][j(8)][lane] -> uint2
__device__ uint2 g_Bhf[256 * 8 * 32];
__device__ uint2 g_Blf[256 * 8 * 32];
__device__ float g_WT[NEXP * DIM];              // [e][k] fp32 for repair
__device__ int g_nflag;
__device__ int g_list[N_TOK];
__device__ int g_cand[N_TOK * NCAND];

// pack two floats into f16x2: low half = e0, high half = e1
__device__ __forceinline__ uint32_t pack_h2(float e0, float e1) {
    __half2 h = __floats2half2_rn(e0, e1);
    return *(uint32_t*)&h;
}
__device__ __forceinline__ float h2_lo(uint32_t u) {
    return __half2float(((__half2*)&u)->x);
}
__device__ __forceinline__ float h2_hi(uint32_t u) {
    return __half2float(((__half2*)&u)->y);
}

__device__ __forceinline__ void mma_f16(float* c,
                                        uint32_t a0, uint32_t a1, uint32_t a2, uint32_t a3,
                                        uint32_t b0, uint32_t b1) {
    asm volatile(
        "mma.sync.aligned.m16n8k16.row.col.f32.f16.f16.f32 "
        "{%0,%1,%2,%3}, {%4,%5,%6,%7}, {%8,%9}, {%0,%1,%2,%3};"
        : "+f"(c[0]), "+f"(c[1]), "+f"(c[2]), "+f"(c[3])
        : "r"(a0), "r"(a1), "r"(a2), "r"(a3), "r"(b0), "r"(b1));
}

// prep: split W into per-lane f16 hi/lo frag layout + fp32 transpose; zeroes
// counters/flags.  p = gstep*256 + j*32 + lane, gstep = global k16 step.
__global__ void prep_W_kernel(const float* __restrict__ W, float* __restrict__ cnt) {
    if (blockIdx.x == 0) {
        if (threadIdx.x < NEXP) cnt[threadIdx.x] = 0.0f;
        if (threadIdx.x == 0) g_nflag = 0;
    }
    int p = blockIdx.x * 256 + threadIdx.x;     // 65536
    int lane  = p & 31;
    int j     = (p >> 5) & 7;
    int gstep = p >> 8;                          // 0..255
    int g2  = lane >> 2;
    int tig = lane & 3;
    int e   = j * 8 + g2;
    int k1 = gstep * 16 + 2 * tig;
    int k2 = k1 + 8;
    float w0 = W[(size_t)k1 * NEXP + e];
    float w1 = W[(size_t)(k1 + 1) * NEXP + e];
    float w2 = W[(size_t)k2 * NEXP + e];
    float w3 = W[(size_t)(k2 + 1) * NEXP + e];
    uint32_t h0 = pack_h2(w0, w1);
    uint32_t h1 = pack_h2(w2, w3);
    uint32_t l0 = pack_h2(w0 - h2_lo(h0), w1 - h2_hi(h0));
    uint32_t l1 = pack_h2(w2 - h2_lo(h1), w3 - h2_hi(h1));
    g_Bhf[p] = make_uint2(h0, h1);
    g_Blf[p] = make_uint2(l0, l1);
    g_WT[(size_t)e * DIM + k1]     = w0;
    g_WT[(size_t)e * DIM + k1 + 1] = w1;
    g_WT[(size_t)e * DIM + k2]     = w2;
    g_WT[(size_t)e * DIM + k2 + 1] = w3;
}

__global__ void __launch_bounds__(THREADS, 8)
router_kernel(const float* __restrict__ x, const float* __restrict__ sbias_g,
              const float* __restrict__ noise, float* __restrict__ out) {
    extern __shared__ char db[];
    __shared__ float s_bias[NEXP];

    const int tid  = threadIdx.x;
    const int wid  = tid >> 5;                // 0..1
    const int lane = tid & 31;
    const int g    = lane >> 2;
    const int tig  = lane & 3;
    const int set  = wid;                     // K-set: which k16 step of chunk
    const int tok0 = blockIdx.x * MT;

    s_bias[tid] = sbias_g[tid];               // THREADS == NEXP == 64

    // staging: thread -> (token 0..15, k-quarter of 8 elems = 4 kp)
    const int t_tok = tid & 15;
    const int t_q   = tid >> 4;               // 0..3
    const float* xg = x     + (size_t)(tok0 + t_tok) * DIM + t_q * 8;
    const float* ng = noise + (size_t)(tok0 + t_tok) * DIM + t_q * 8;

    float acc[8][4];
#pragma unroll
    for (int j = 0; j < 8; ++j)
#pragma unroll
        for (int q = 0; q < 4; ++q) acc[j][q] = 0.0f;

    float4 rx[2], rn[2];
#pragma unroll
    for (int j = 0; j < 2; ++j) {
        rx[j] = *(const float4*)(xg + 4 * j);
        rn[j] = *(const float4*)(ng + 4 * j);
    }

#define STORE_CHUNK(BUF) do {                                                   \
        uint32_t* Ah = (uint32_t*)(db + AHIB(BUF));                             \
        uint32_t* Al = (uint32_t*)(db + ALOB(BUF));                             \
        _Pragma("unroll")                                                       \
        for (int j = 0; j < 2; ++j) {                                           \
            float v0 = rx[j].x * (0.99f + rn[j].x * 0.02f);                     \
            float v1 = rx[j].y * (0.99f + rn[j].y * 0.02f);                     \
            float v2 = rx[j].z * (0.99f + rn[j].z * 0.02f);                     \
            float v3 = rx[j].w * (0.99f + rn[j].w * 0.02f);                     \
            uint32_t h0 = pack_h2(v0, v1);                                      \
            uint32_t h1 = pack_h2(v2, v3);                                      \
            uint32_t l0 = pack_h2(v0 - h2_lo(h0), v1 - h2_hi(h0));              \
            uint32_t l1 = pack_h2(v2 - h2_lo(h1), v3 - h2_hi(h1));              \
            int kp0 = t_q * 4 + 2 * j;                                          \
            Ah[AW(kp0, t_tok)]     = h0;                                        \
            Ah[AW(kp0 + 1, t_tok)] = h1;                                        \
            Al[AW(kp0, t_tok)]     = l0;                                        \
            Al[AW(kp0 + 1, t_tok)] = l1;                                        \
        }                                                                       \
    } while (0)

    STORE_CHUNK(0);
    __syncthreads();

#pragma unroll 1
    for (int c = 0; c < NCHUNK; ++c) {
        const int buf = c & 1;
        const bool more = (c + 1 < NCHUNK);

        if (more) {
            const int cb = (c + 1) * KC;
#pragma unroll
            for (int j = 0; j < 2; ++j) {
                rx[j] = *(const float4*)(xg + cb + 4 * j);
                rn[j] = *(const float4*)(ng + cb + 4 * j);
            }
        }

        // ---- my k16 step: B frags from L2, A frags from smem ----
        {
            const size_t gstep = (size_t)c * 2 + set;
            const uint2* Bh = g_Bhf + gstep * 256 + lane;
            const uint2* Bl = g_Blf + gstep * 256 + lane;
            uint2 b[8];
#pragma unroll
            for (int j = 0; j < 8; ++j) b[j] = __ldg(Bh + j * 32);

            const uint32_t* Ah = (const uint32_t*)(db + AHIB(buf));
            const uint32_t* Al = (const uint32_t*)(db + ALOB(buf));
            const int kb = set * 8;
            uint32_t ah[4], al[4];
            ah[0] = Ah[AW(kb + tig, g)];
            ah[1] = Ah[AW(kb + tig, g + 8)];
            ah[2] = Ah[AW(kb + tig + 4, g)];
            ah[3] = Ah[AW(kb + tig + 4, g + 8)];
            al[0] = Al[AW(kb + tig, g)];
            al[1] = Al[AW(kb + tig, g + 8)];
            al[2] = Al[AW(kb + tig + 4, g)];
            al[3] = Al[AW(kb + tig + 4, g + 8)];

            // T1: a_hi * b_hi
#pragma unroll
            for (int j = 0; j < 8; ++j)
                mma_f16(acc[j], ah[0], ah[1], ah[2], ah[3], b[j].x, b[j].y);
            // T3: a_lo * b_hi
#pragma unroll
            for (int j = 0; j < 8; ++j)
                mma_f16(acc[j], al[0], al[1], al[2], al[3], b[j].x, b[j].y);
            // T2: a_hi * b_lo (reuse b regs)
#pragma unroll
            for (int j = 0; j < 8; ++j) b[j] = __ldg(Bl + j * 32);
#pragma unroll
            for (int j = 0; j < 8; ++j)
                mma_f16(acc[j], ah[0], ah[1], ah[2], ah[3], b[j].x, b[j].y);
        }

        // store chunk c+1 into buf^1 (disjoint from buf; prior readers of
        // buf^1 were fenced by chunk c-1's barrier)
        if (more) STORE_CHUNK(buf ^ 1);
        __syncthreads();
    }

    // ---- epilogue: K-set reduction into L[16][65] (overlays staging) ----
    float* L = (float*)db;
    if (set == 0) {
#pragma unroll
        for (int j = 0; j < 8; ++j) {
            int r = g, cb = j * 8 + tig * 2;
            L[r * 65 + cb]           = acc[j][0];
            L[r * 65 + cb + 1]       = acc[j][1];
            L[(r + 8) * 65 + cb]     = acc[j][2];
            L[(r + 8) * 65 + cb + 1] = acc[j][3];
        }
    }
    __syncthreads();
    if (set == 1) {
#pragma unroll
        for (int j = 0; j < 8; ++j) {
            int r = g, cb = j * 8 + tig * 2;
            L[r * 65 + cb]           += acc[j][0];
            L[r * 65 + cb + 1]       += acc[j][1];
            L[(r + 8) * 65 + cb]     += acc[j][2];
            L[(r + 8) * 65 + cb + 1] += acc[j][3];
        }
    }
    __syncthreads();

    float* gL = out + OFF_LOGITS + (size_t)tok0 * NEXP;
    for (int idx = tid; idx < MT * NEXP; idx += THREADS)
        gL[idx] = L[(idx >> 6) * 65 + (idx & 63)];
    __syncthreads();

    if (tid < MT) {
        float* row = L + tid * 65;
        float mx = row[0];
#pragma unroll 8
        for (int e = 1; e < NEXP; ++e) mx = fmaxf(mx, row[e]);
        float s = 0.0f;
#pragma unroll 8
        for (int e = 0; e < NEXP; ++e) s += expf(row[e] - mx);
        float inv = 1.0f / s;
#pragma unroll 8
        for (int e = 0; e < NEXP; ++e) row[e] = expf(row[e] - mx) * inv;
    }
    __syncthreads();

    float* gS = out + OFF_SCORES + (size_t)tok0 * NEXP;
    for (int idx = tid; idx < MT * NEXP; idx += THREADS)
        gS[idx] = L[(idx >> 6) * 65 + (idx & 63)];

    // top-12 biased ranking; write top-8; flag near-ties for exact-fp32 repair
    if (tid < MT) {
        const float* rp = L + tid * 65;
        float bv[NCAND];
        int   bix[NCAND];
        u64 mask = 0ull;
#pragma unroll
        for (int k = 0; k < NCAND; ++k) {
            float best = -1e30f;
            int bi = 0;
            for (int e = 0; e < NEXP; ++e) {
                if (!((mask >> e) & 1ull)) {
                    float v = rp[e] + s_bias[e];
                    if (v > best) { best = v; bi = e; }
                }
            }
            mask |= 1ull << bi;
            bv[k] = best;
            bix[k] = bi;
        }
        float w[TOPK], ss = 0.0f;
#pragma unroll
        for (int k = 0; k < TOPK; ++k) { w[k] = rp[bix[k]]; ss += w[k] * w[k]; }
        float winv = 1.0f / sqrtf(ss);

        const int tok = tok0 + tid;
        float* gW = out + OFF_W   + (size_t)tok * TOPK;
        float* gI = out + OFF_IDX + (size_t)tok * TOPK;
#pragma unroll
        for (int k = 0; k < TOPK; ++k) {
            gW[k] = w[k] * winv;
            gI[k] = (float)bix[k];
        }

        float ming = bv[0] - bv[1];
#pragma unroll
        for (int j = 1; j < 8; ++j) ming = fminf(ming, bv[j] - bv[j + 1]);
        if (ming < THRESH) {
            int pos = atomicAdd(&g_nflag, 1);
            g_list[pos] = tok;
#pragma unroll
            for (int j = 0; j < NCAND; ++j) g_cand[tok * NCAND + j] = bix[j];
        }
    }
}

// Repair: recompute 12 candidate logits in exact fp32 for flagged tokens,
// re-rank, rewrite indices + weights (weights gathered from MMA scores row).
__global__ void __launch_bounds__(384, 2)
repair_kernel(const float* __restrict__ x, const float* __restrict__ sbias_g,
              const float* __restrict__ noise, float* __restrict__ out) {
    __shared__ float sxj[DIM];
    __shared__ float sl[NCAND];
    __shared__ int   se[NCAND];

    const int tid  = threadIdx.x;
    const int wid  = tid >> 5;
    const int lane = tid & 31;
    const int n    = g_nflag;

    for (int i = blockIdx.x; i < n; i += gridDim.x) {
        const int tok = g_list[i];
        __syncthreads();

        const float* xr = x     + (size_t)tok * DIM;
        const float* nr = noise + (size_t)tok * DIM;
        for (int idx = tid; idx < DIM; idx += 384)
            sxj[idx] = xr[idx] * (0.99f + nr[idx] * 0.02f);
        __syncthreads();

        if (wid < NCAND) {
            const int e = g_cand[tok * NCAND + wid];
            const float* wt = g_WT + (size_t)e * DIM;
            float a = 0.0f;
            for (int k = lane; k < DIM; k += 32 * 4) {
                a += sxj[k]       * wt[k];
                a += sxj[k + 32]  * wt[k + 32];
                a += sxj[k + 64]  * wt[k + 64];
                a += sxj[k + 96]  * wt[k + 96];
            }
#pragma unroll
            for (int o = 16; o; o >>= 1) a += __shfl_xor_sync(0xFFFFFFFFu, a, o);
            if (lane == 0) { sl[wid] = a; se[wid] = e; }
        }
        __syncthreads();

        if (tid == 0) {
            float mxl = sl[0];
#pragma unroll
            for (int j = 1; j < NCAND; ++j) mxl = fmaxf(mxl, sl[j]);
            float s0 = out[OFF_SCORES + (size_t)tok * NEXP + se[0]];
            float C = s0 / expf(sl[0] - mxl);
            float bval[NCAND];
#pragma unroll
            for (int j = 0; j < NCAND; ++j)
                bval[j] = expf(sl[j] - mxl) * C + sbias_g[se[j]];

            int ix[TOPK];
            unsigned m2 = 0;
#pragma unroll
            for (int k = 0; k < TOPK; ++k) {
                float best = -1e30f;
                int bj = 0, beste = NEXP;
                for (int j = 0; j < NCAND; ++j) {
                    if (!((m2 >> j) & 1u)) {
                        float v = bval[j];
                        int e = se[j];
                        if (v > best || (v == best && e < beste)) {
                            best = v; bj = j; beste = e;
                        }
                    }
                }
                m2 |= 1u << bj;
                ix[k] = se[bj];
            }
            float w[TOPK], ss = 0.0f;
#pragma unroll
            for (int k = 0; k < TOPK; ++k) {
                w[k] = out[OFF_SCORES + (size_t)tok * NEXP + ix[k]];
                ss += w[k] * w[k];
            }
            float winv = 1.0f / sqrtf(ss);
            float* gW = out + OFF_W   + (size_t)tok * TOPK;
            float* gI = out + OFF_IDX + (size_t)tok * TOPK;
#pragma unroll
            for (int k = 0; k < TOPK; ++k) {
                gW[k] = w[k] * winv;
                gI[k] = (float)ix[k];
            }
        }
    }
}

__global__ void bincount_kernel(const float* __restrict__ gI, float* __restrict__ cnt) {
    __shared__ int h[NEXP];
    const int tid = threadIdx.x;
    if (tid < NEXP) h[tid] = 0;
    __syncthreads();
    for (int idx = blockIdx.x * blockDim.x + tid; idx < N_TOK * TOPK;
         idx += gridDim.x * blockDim.x)
        atomicAdd(&h[(int)gI[idx]], 1);
    __syncthreads();
    if (tid < NEXP && h[tid]) atomicAdd(&cnt[tid], (float)h[tid]);
}

extern "C" void kernel_launch(void* const* d_in, const int* in_sizes, int n_in,
                              void* d_out, int out_size) {
    const float* x     = (const float*)d_in[0];
    const float* W     = (const float*)d_in[1];
    const float* sbias = (const float*)d_in[2];
    const float* noise = (const float*)d_in[3];
    float* out = (float*)d_out;

    prep_W_kernel<<<256, 256>>>(W, out + OFF_CNT);
    router_kernel<<<NBLK, THREADS, SMEM_BYTES>>>(x, sbias, noise, out);
    repair_kernel<<<1024, 384>>>(x, sbias, noise, out);
    bincount_kernel<<<256, 256>>>(out + OFF_IDX, out + OFF_CNT);
}

// round 15
// speedup vs baseline: 1.1749x; 1.0009x over previous
#include <cuda_runtime.h>
#include <cuda_fp16.h>
#include <cstdint>

// MoE router: jitter -> GEMM (16384x4096 @ 4096x64) -> softmax -> biased top-8
// -> L2-norm weights -> bincount.  GEMM via mma.sync.m16n8k16.f16 (f32 accum),
// 3xFP16 split (22 mantissa bits -> logit noise ~1e-6, THRESH=1e-6).
// MT=16, 8 CTAs/SM (grid 1024, 64 thr).  bh AND bl B-frags hoisted to chunk
// start so T1+T3 (16 MMAs) cover bl's L2 latency.  Bincount folded into
// router (smem counts -> global atomics) + repair (delta fixups).

#define N_TOK   16384
#define DIM     4096
#define NEXP    64
#define TOPK    8
#define NCAND   12
#define MT      16
#define KC      32              // K per chunk = 16 kp words = 2 k16-steps
#define NCHUNK  (DIM / KC)      // 128
#define THREADS 64
#define NBLK    (N_TOK / MT)    // 1024
#define THRESH  1e-6f

#define OFF_LOGITS 0
#define OFF_SCORES (N_TOK * NEXP)
#define OFF_W      (2 * N_TOK * NEXP)
#define OFF_IDX    (2 * N_TOK * NEXP + N_TOK * TOPK)
#define OFF_CNT    (2 * N_TOK * NEXP + 2 * N_TOK * TOPK)

// dynamic smem: A planes, double buffered. per buf: hi 1KB + lo 1KB.
// Epilogue L[16][65] (4160B) overlays.
#define AHIB(b) ((b) * 2048)
#define ALOB(b) ((b) * 2048 + 1024)
#define SMEM_BYTES 4480

typedef unsigned long long u64;

// word index within a 256-word A plane (16 kp x 16 tok).
#define AW(kp, tok) ((((kp) * 16) + (tok)) ^ (((kp) & 4) << 2))

// B frags per-lane, linear in global k16-step: [gstep(256)][j(8)][lane] -> uint2
__device__ uint2 g_Bhf[256 * 8 * 32];
__device__ uint2 g_Blf[256 * 8 * 32];
__device__ float g_WT[NEXP * DIM];              // [e][k] fp32 for repair
__device__ int g_nflag;
__device__ int g_list[N_TOK];
__device__ int g_cand[N_TOK * NCAND];

__device__ __forceinline__ uint32_t pack_h2(float e0, float e1) {
    __half2 h = __floats2half2_rn(e0, e1);
    return *(uint32_t*)&h;
}
__device__ __forceinline__ float h2_lo(uint32_t u) {
    return __half2float(((__half2*)&u)->x);
}
__device__ __forceinline__ float h2_hi(uint32_t u) {
    return __half2float(((__half2*)&u)->y);
}

__device__ __forceinline__ void mma_f16(float* c,
                                        uint32_t a0, uint32_t a1, uint32_t a2, uint32_t a3,
                                        uint32_t b0, uint32_t b1) {
    asm volatile(
        "mma.sync.aligned.m16n8k16.row.col.f32.f16.f16.f32 "
        "{%0,%1,%2,%3}, {%4,%5,%6,%7}, {%8,%9}, {%0,%1,%2,%3};"
        : "+f"(c[0]), "+f"(c[1]), "+f"(c[2]), "+f"(c[3])
        : "r"(a0), "r"(a1), "r"(a2), "r"(a3), "r"(b0), "r"(b1));
}

// prep: split W into per-lane f16 hi/lo frag layout + fp32 transpose; zeroes
// counters/flags.
__global__ void prep_W_kernel(const float* __restrict__ W, float* __restrict__ cnt) {
    if (blockIdx.x == 0) {
        if (threadIdx.x < NEXP) cnt[threadIdx.x] = 0.0f;
        if (threadIdx.x == 0) g_nflag = 0;
    }
    int p = blockIdx.x * 256 + threadIdx.x;     // 65536
    int lane  = p & 31;
    int j     = (p >> 5) & 7;
    int gstep = p >> 8;                          // 0..255
    int g2  = lane >> 2;
    int tig = lane & 3;
    int e   = j * 8 + g2;
    int k1 = gstep * 16 + 2 * tig;
    int k2 = k1 + 8;
    float w0 = W[(size_t)k1 * NEXP + e];
    float w1 = W[(size_t)(k1 + 1) * NEXP + e];
    float w2 = W[(size_t)k2 * NEXP + e];
    float w3 = W[(size_t)(k2 + 1) * NEXP + e];
    uint32_t h0 = pack_h2(w0, w1);
    uint32_t h1 = pack_h2(w2, w3);
    uint32_t l0 = pack_h2(w0 - h2_lo(h0), w1 - h2_hi(h0));
    uint32_t l1 = pack_h2(w2 - h2_lo(h1), w3 - h2_hi(h1));
    g_Bhf[p] = make_uint2(h0, h1);
    g_Blf[p] = make_uint2(l0, l1);
    g_WT[(size_t)e * DIM + k1]     = w0;
    g_WT[(size_t)e * DIM + k1 + 1] = w1;
    g_WT[(size_t)e * DIM + k2]     = w2;
    g_WT[(size_t)e * DIM + k2 + 1] = w3;
}

__global__ void __launch_bounds__(THREADS, 8)
router_kernel(const float* __restrict__ x, const float* __restrict__ sbias_g,
              const float* __restrict__ noise, float* __restrict__ out) {
    extern __shared__ char db[];
    __shared__ float s_bias[NEXP];
    __shared__ float s_cnt[NEXP];

    const int tid  = threadIdx.x;
    const int wid  = tid >> 5;                // 0..1
    const int lane = tid & 31;
    const int g    = lane >> 2;
    const int tig  = lane & 3;
    const int set  = wid;                     // K-set: which k16 step of chunk
    const int tok0 = blockIdx.x * MT;

    s_bias[tid] = sbias_g[tid];               // THREADS == NEXP == 64
    s_cnt[tid]  = 0.0f;

    // staging: thread -> (token 0..15, k-quarter of 8 elems = 4 kp)
    const int t_tok = tid & 15;
    const int t_q   = tid >> 4;               // 0..3
    const float* xg = x     + (size_t)(tok0 + t_tok) * DIM + t_q * 8;
    const float* ng = noise + (size_t)(tok0 + t_tok) * DIM + t_q * 8;

    float acc[8][4];
#pragma unroll
    for (int j = 0; j < 8; ++j)
#pragma unroll
        for (int q = 0; q < 4; ++q) acc[j][q] = 0.0f;

    float4 rx[2], rn[2];
#pragma unroll
    for (int j = 0; j < 2; ++j) {
        rx[j] = *(const float4*)(xg + 4 * j);
        rn[j] = *(const float4*)(ng + 4 * j);
    }

#define STORE_CHUNK(BUF) do {                                                   \
        uint32_t* Ah = (uint32_t*)(db + AHIB(BUF));                             \
        uint32_t* Al = (uint32_t*)(db + ALOB(BUF));                             \
        _Pragma("unroll")                                                       \
        for (int j = 0; j < 2; ++j) {                                           \
            float v0 = rx[j].x * (0.99f + rn[j].x * 0.02f);                     \
            float v1 = rx[j].y * (0.99f + rn[j].y * 0.02f);                     \
            float v2 = rx[j].z * (0.99f + rn[j].z * 0.02f);                     \
            float v3 = rx[j].w * (0.99f + rn[j].w * 0.02f);                     \
            uint32_t h0 = pack_h2(v0, v1);                                      \
            uint32_t h1 = pack_h2(v2, v3);                                      \
            uint32_t l0 = pack_h2(v0 - h2_lo(h0), v1 - h2_hi(h0));              \
            uint32_t l1 = pack_h2(v2 - h2_lo(h1), v3 - h2_hi(h1));              \
            int kp0 = t_q * 4 + 2 * j;                                          \
            Ah[AW(kp0, t_tok)]     = h0;                                        \
            Ah[AW(kp0 + 1, t_tok)] = h1;                                        \
            Al[AW(kp0, t_tok)]     = l0;                                        \
            Al[AW(kp0 + 1, t_tok)] = l1;                                        \
        }                                                                       \
    } while (0)

    STORE_CHUNK(0);
    __syncthreads();

#pragma unroll 1
    for (int c = 0; c < NCHUNK; ++c) {
        const int buf = c & 1;
        const bool more = (c + 1 < NCHUNK);

        if (more) {
            const int cb = (c + 1) * KC;
#pragma unroll
            for (int j = 0; j < 2; ++j) {
                rx[j] = *(const float4*)(xg + cb + 4 * j);
                rn[j] = *(const float4*)(ng + cb + 4 * j);
            }
        }

        // ---- my k16 step: ALL B frags issued up front (bl covered by T1+T3) ----
        {
            const size_t gstep = (size_t)c * 2 + set;
            const uint2* Bh = g_Bhf + gstep * 256 + lane;
            const uint2* Bl = g_Blf + gstep * 256 + lane;
            uint2 bh[8], bl[8];
#pragma unroll
            for (int j = 0; j < 8; ++j) bh[j] = __ldg(Bh + j * 32);
#pragma unroll
            for (int j = 0; j < 8; ++j) bl[j] = __ldg(Bl + j * 32);

            const uint32_t* Ah = (const uint32_t*)(db + AHIB(buf));
            const uint32_t* Al = (const uint32_t*)(db + ALOB(buf));
            const int kb = set * 8;
            uint32_t ah[4], al[4];
            ah[0] = Ah[AW(kb + tig, g)];
            ah[1] = Ah[AW(kb + tig, g + 8)];
            ah[2] = Ah[AW(kb + tig + 4, g)];
            ah[3] = Ah[AW(kb + tig + 4, g + 8)];
            al[0] = Al[AW(kb + tig, g)];
            al[1] = Al[AW(kb + tig, g + 8)];
            al[2] = Al[AW(kb + tig + 4, g)];
            al[3] = Al[AW(kb + tig + 4, g + 8)];

            // T1: a_hi * b_hi
#pragma unroll
            for (int j = 0; j < 8; ++j)
                mma_f16(acc[j], ah[0], ah[1], ah[2], ah[3], bh[j].x, bh[j].y);
            // T3: a_lo * b_hi
#pragma unroll
            for (int j = 0; j < 8; ++j)
                mma_f16(acc[j], al[0], al[1], al[2], al[3], bh[j].x, bh[j].y);
            // T2: a_hi * b_lo
#pragma unroll
            for (int j = 0; j < 8; ++j)
                mma_f16(acc[j], ah[0], ah[1], ah[2], ah[3], bl[j].x, bl[j].y);
        }

        if (more) STORE_CHUNK(buf ^ 1);
        __syncthreads();
    }

    // ---- epilogue: K-set reduction into L[16][65] (overlays staging) ----
    float* L = (float*)db;
    if (set == 0) {
#pragma unroll
        for (int j = 0; j < 8; ++j) {
            int r = g, cb = j * 8 + tig * 2;
            L[r * 65 + cb]           = acc[j][0];
            L[r * 65 + cb + 1]       = acc[j][1];
            L[(r + 8) * 65 + cb]     = acc[j][2];
            L[(r + 8) * 65 + cb + 1] = acc[j][3];
        }
    }
    __syncthreads();
    if (set == 1) {
#pragma unroll
        for (int j = 0; j < 8; ++j) {
            int r = g, cb = j * 8 + tig * 2;
            L[r * 65 + cb]           += acc[j][0];
            L[r * 65 + cb + 1]       += acc[j][1];
            L[(r + 8) * 65 + cb]     += acc[j][2];
            L[(r + 8) * 65 + cb + 1] += acc[j][3];
        }
    }
    __syncthreads();

    float* gL = out + OFF_LOGITS + (size_t)tok0 * NEXP;
    for (int idx = tid; idx < MT * NEXP; idx += THREADS)
        gL[idx] = L[(idx >> 6) * 65 + (idx & 63)];
    __syncthreads();

    if (tid < MT) {
        float* row = L + tid * 65;
        float mx = row[0];
#pragma unroll 8
        for (int e = 1; e < NEXP; ++e) mx = fmaxf(mx, row[e]);
        float s = 0.0f;
#pragma unroll 8
        for (int e = 0; e < NEXP; ++e) s += expf(row[e] - mx);
        float inv = 1.0f / s;
#pragma unroll 8
        for (int e = 0; e < NEXP; ++e) row[e] = expf(row[e] - mx) * inv;
    }
    __syncthreads();

    float* gS = out + OFF_SCORES + (size_t)tok0 * NEXP;
    for (int idx = tid; idx < MT * NEXP; idx += THREADS)
        gS[idx] = L[(idx >> 6) * 65 + (idx & 63)];

    // top-12 biased ranking; write top-8; smem counts; flag near-ties
    if (tid < MT) {
        const float* rp = L + tid * 65;
        float bv[NCAND];
        int   bix[NCAND];
        u64 mask = 0ull;
#pragma unroll
        for (int k = 0; k < NCAND; ++k) {
            float best = -1e30f;
            int bi = 0;
            for (int e = 0; e < NEXP; ++e) {
                if (!((mask >> e) & 1ull)) {
                    float v = rp[e] + s_bias[e];
                    if (v > best) { best = v; bi = e; }
                }
            }
            mask |= 1ull << bi;
            bv[k] = best;
            bix[k] = bi;
        }
        float w[TOPK], ss = 0.0f;
#pragma unroll
        for (int k = 0; k < TOPK; ++k) { w[k] = rp[bix[k]]; ss += w[k] * w[k]; }
        float winv = 1.0f / sqrtf(ss);

        const int tok = tok0 + tid;
        float* gW = out + OFF_W   + (size_t)tok * TOPK;
        float* gI = out + OFF_IDX + (size_t)tok * TOPK;
#pragma unroll
        for (int k = 0; k < TOPK; ++k) {
            gW[k] = w[k] * winv;
            gI[k] = (float)bix[k];
            atomicAdd(&s_cnt[bix[k]], 1.0f);
        }

        float ming = bv[0] - bv[1];
#pragma unroll
        for (int j = 1; j < 8; ++j) ming = fminf(ming, bv[j] - bv[j + 1]);
        if (ming < THRESH) {
            int pos = atomicAdd(&g_nflag, 1);
            g_list[pos] = tok;
#pragma unroll
            for (int j = 0; j < NCAND; ++j) g_cand[tok * NCAND + j] = bix[j];
        }
    }
    __syncthreads();

    // flush per-CTA counts (integer-valued floats: exact, order-free)
    {
        float cc = s_cnt[tid];
        if (cc != 0.0f) atomicAdd(out + OFF_CNT + tid, cc);
    }
}

// Repair: recompute 12 candidate logits in exact fp32 for flagged tokens,
// re-rank, rewrite indices + weights, and patch the expert counts by delta.
__global__ void __launch_bounds__(384, 2)
repair_kernel(const float* __restrict__ x, const float* __restrict__ sbias_g,
              const float* __restrict__ noise, float* __restrict__ out) {
    __shared__ float sxj[DIM];
    __shared__ float sl[NCAND];
    __shared__ int   se[NCAND];

    const int tid  = threadIdx.x;
    const int wid  = tid >> 5;
    const int lane = tid & 31;
    const int n    = g_nflag;

    for (int i = blockIdx.x; i < n; i += gridDim.x) {
        const int tok = g_list[i];
        __syncthreads();

        const float* xr = x     + (size_t)tok * DIM;
        const float* nr = noise + (size_t)tok * DIM;
        for (int idx = tid; idx < DIM; idx += 384)
            sxj[idx] = xr[idx] * (0.99f + nr[idx] * 0.02f);
        __syncthreads();

        if (wid < NCAND) {
            const int e = g_cand[tok * NCAND + wid];
            const float* wt = g_WT + (size_t)e * DIM;
            float a = 0.0f;
            for (int k = lane; k < DIM; k += 32 * 4) {
                a += sxj[k]       * wt[k];
                a += sxj[k + 32]  * wt[k + 32];
                a += sxj[k + 64]  * wt[k + 64];
                a += sxj[k + 96]  * wt[k + 96];
            }
#pragma unroll
            for (int o = 16; o; o >>= 1) a += __shfl_xor_sync(0xFFFFFFFFu, a, o);
            if (lane == 0) { sl[wid] = a; se[wid] = e; }
        }
        __syncthreads();

        if (tid == 0) {
            float mxl = sl[0];
#pragma unroll
            for (int j = 1; j < NCAND; ++j) mxl = fmaxf(mxl, sl[j]);
            float s0 = out[OFF_SCORES + (size_t)tok * NEXP + se[0]];
            float C = s0 / expf(sl[0] - mxl);
            float bval[NCAND];
#pragma unroll
            for (int j = 0; j < NCAND; ++j)
                bval[j] = expf(sl[j] - mxl) * C + sbias_g[se[j]];

            int ix[TOPK];
            unsigned m2 = 0;
#pragma unroll
            for (int k = 0; k < TOPK; ++k) {
                float best = -1e30f;
                int bj = 0, beste = NEXP;
                for (int j = 0; j < NCAND; ++j) {
                    if (!((m2 >> j) & 1u)) {
                        float v = bval[j];
                        int e = se[j];
                        if (v > best || (v == best && e < beste)) {
                            best = v; bj = j; beste = e;
                        }
                    }
                }
                m2 |= 1u << bj;
                ix[k] = se[bj];
            }
            float w[TOPK], ss = 0.0f;
#pragma unroll
            for (int k = 0; k < TOPK; ++k) {
                w[k] = out[OFF_SCORES + (size_t)tok * NEXP + ix[k]];
                ss += w[k] * w[k];
            }
            float winv = 1.0f / sqrtf(ss);
            float* gW = out + OFF_W   + (size_t)tok * TOPK;
            float* gI = out + OFF_IDX + (size_t)tok * TOPK;
            float* cnt = out + OFF_CNT;
#pragma unroll
            for (int k = 0; k < TOPK; ++k) {
                int oldix = (int)gI[k];
                if (oldix != ix[k]) {
                    atomicAdd(cnt + oldix, -1.0f);
                    atomicAdd(cnt + ix[k],  1.0f);
                }
                gW[k] = w[k] * winv;
                gI[k] = (float)ix[k];
            }
        }
    }
}

extern "C" void kernel_launch(void* const* d_in, const int* in_sizes, int n_in,
                              void* d_out, int out_size) {
    const float* x     = (const float*)d_in[0];
    const float* W     = (const float*)d_in[1];
    const float* sbias = (const float*)d_in[2];
    const float* noise = (const float*)d_in[3];
    float* out = (float*)d_out;

    prep_W_kernel<<<256, 256>>>(W, out + OFF_CNT);
    router_kernel<<<NBLK, THREADS, SMEM_BYTES>>>(x, sbias, noise, out);
    repair_kernel<<<256, 384>>>(x, sbias, noise, out);
}

// round 16
// speedup vs baseline: 1.3724x; 1.1681x over previous
#include <cuda_runtime.h>
#include <cuda_fp16.h>
#include <cstdint>

// MoE router: jitter -> GEMM (16384x4096 @ 4096x64) -> softmax -> biased top-8
// -> L2-norm weights -> bincount.  GEMM via mma.sync.m16n8k16.f16 (f32 accum),
// 3xFP16 split.  MT=16, 8 CTAs/SM (grid 1024, 64 thr).
// COALESCED STAGING: lane l reads col l of 8 token rows (1 wavefront per
// request vs 16 for the old float4 pattern); pair packing via shfl_xor.
// Bincount folded into router + repair deltas.  Near-ties repaired in fp32.

#define N_TOK   16384
#define DIM     4096
#define NEXP    64
#define TOPK    8
#define NCAND   12
#define MT      16
#define KC      32              // K per chunk = 16 kp words = 2 k16-steps
#define NCHUNK  (DIM / KC)      // 128
#define THREADS 64
#define NBLK    (N_TOK / MT)    // 1024
#define THRESH  1e-6f

#define OFF_LOGITS 0
#define OFF_SCORES (N_TOK * NEXP)
#define OFF_W      (2 * N_TOK * NEXP)
#define OFF_IDX    (2 * N_TOK * NEXP + N_TOK * TOPK)
#define OFF_CNT    (2 * N_TOK * NEXP + 2 * N_TOK * TOPK)

// dynamic smem: A planes, double buffered. per buf: hi 1KB + lo 1KB.
// Epilogue L[16][65] (4160B) overlays.
#define AHIB(b) ((b) * 2048)
#define ALOB(b) ((b) * 2048 + 1024)
#define SMEM_BYTES 4480

typedef unsigned long long u64;

// plane word index: 16 kp x 16 tok with token-permute swizzle.
// PERM uses kp bits 1,2,3 mapped to tok bits 0,1,3 (bit2 unused so
// perm(kp)^perm(kp') != 4 = t_even^t_odd): STS conflict-free, LDS <=2-way.
#define PERM(kp) (((((kp) >> 1) & 1)) | ((((kp) >> 2) & 1) << 1) | ((((kp) >> 3) & 1) << 3))
#define AW2(kp, tok) ((kp) * 16 + ((tok) ^ PERM(kp)))

// B frags per-lane, linear in global k16-step: [gstep(256)][j(8)][lane] -> uint2
__device__ uint2 g_Bhf[256 * 8 * 32];
__device__ uint2 g_Blf[256 * 8 * 32];
__device__ float g_WT[NEXP * DIM];              // [e][k] fp32 for repair
__device__ int g_nflag;
__device__ int g_list[N_TOK];
__device__ int g_cand[N_TOK * NCAND];

__device__ __forceinline__ uint32_t pack_h2(float e0, float e1) {
    __half2 h = __floats2half2_rn(e0, e1);
    return *(uint32_t*)&h;
}
__device__ __forceinline__ float h2_lo(uint32_t u) {
    return __half2float(((__half2*)&u)->x);
}
__device__ __forceinline__ float h2_hi(uint32_t u) {
    return __half2float(((__half2*)&u)->y);
}

__device__ __forceinline__ void mma_f16(float* c,
                                        uint32_t a0, uint32_t a1, uint32_t a2, uint32_t a3,
                                        uint32_t b0, uint32_t b1) {
    asm volatile(
        "mma.sync.aligned.m16n8k16.row.col.f32.f16.f16.f32 "
        "{%0,%1,%2,%3}, {%4,%5,%6,%7}, {%8,%9}, {%0,%1,%2,%3};"
        : "+f"(c[0]), "+f"(c[1]), "+f"(c[2]), "+f"(c[3])
        : "r"(a0), "r"(a1), "r"(a2), "r"(a3), "r"(b0), "r"(b1));
}

// prep: split W into per-lane f16 hi/lo frag layout + fp32 transpose; zeroes
// counters/flags.
__global__ void prep_W_kernel(const float* __restrict__ W, float* __restrict__ cnt) {
    if (blockIdx.x == 0) {
        if (threadIdx.x < NEXP) cnt[threadIdx.x] = 0.0f;
        if (threadIdx.x == 0) g_nflag = 0;
    }
    int p = blockIdx.x * 256 + threadIdx.x;     // 65536
    int lane  = p & 31;
    int j     = (p >> 5) & 7;
    int gstep = p >> 8;                          // 0..255
    int g2  = lane >> 2;
    int tig = lane & 3;
    int e   = j * 8 + g2;
    int k1 = gstep * 16 + 2 * tig;
    int k2 = k1 + 8;
    float w0 = W[(size_t)k1 * NEXP + e];
    float w1 = W[(size_t)(k1 + 1) * NEXP + e];
    float w2 = W[(size_t)k2 * NEXP + e];
    float w3 = W[(size_t)(k2 + 1) * NEXP + e];
    uint32_t h0 = pack_h2(w0, w1);
    uint32_t h1 = pack_h2(w2, w3);
    uint32_t l0 = pack_h2(w0 - h2_lo(h0), w1 - h2_hi(h0));
    uint32_t l1 = pack_h2(w2 - h2_lo(h1), w3 - h2_hi(h1));
    g_Bhf[p] = make_uint2(h0, h1);
    g_Blf[p] = make_uint2(l0, l1);
    g_WT[(size_t)e * DIM + k1]     = w0;
    g_WT[(size_t)e * DIM + k1 + 1] = w1;
    g_WT[(size_t)e * DIM + k2]     = w2;
    g_WT[(size_t)e * DIM + k2 + 1] = w3;
}

__global__ void __launch_bounds__(THREADS, 8)
router_kernel(const float* __restrict__ x, const float* __restrict__ sbias_g,
              const float* __restrict__ noise, float* __restrict__ out) {
    extern __shared__ char db[];
    __shared__ float s_bias[NEXP];
    __shared__ float s_cnt[NEXP];

    const int tid  = threadIdx.x;
    const int wid  = tid >> 5;                // 0..1
    const int lane = tid & 31;
    const int g    = lane >> 2;
    const int tig  = lane & 3;
    const int set  = wid;                     // K-set AND staging token group
    const int tok0 = blockIdx.x * MT;

    s_bias[tid] = sbias_g[tid];               // THREADS == NEXP == 64
    s_cnt[tid]  = 0.0f;

    // coalesced staging: warp `set` covers tokens set*8..set*8+7; lane l
    // reads column l of each row (one 128B line per warp request).
    const float* xg = x     + (size_t)(tok0 + set * 8) * DIM + lane;
    const float* ng = noise + (size_t)(tok0 + set * 8) * DIM + lane;
    const int s_odd = lane & 1;
    const int s_kp  = lane >> 1;              // pair index 0..15

    float acc[8][4];
#pragma unroll
    for (int j = 0; j < 8; ++j)
#pragma unroll
        for (int q = 0; q < 4; ++q) acc[j][q] = 0.0f;

    float vx[8], vn[8];
#pragma unroll
    for (int r = 0; r < 8; ++r) {
        vx[r] = xg[(size_t)r * DIM];
        vn[r] = ng[(size_t)r * DIM];
    }

    // jitter, pair-exchange via shfl, fp16 hi/lo split, store my half of rows
#define STORE_CHUNK(BUF) do {                                                   \
        uint32_t* Ah = (uint32_t*)(db + AHIB(BUF));                             \
        uint32_t* Al = (uint32_t*)(db + ALOB(BUF));                             \
        _Pragma("unroll")                                                       \
        for (int r = 0; r < 8; ++r) {                                           \
            float v = vx[r] * (0.99f + vn[r] * 0.02f);                          \
            float u = __shfl_xor_sync(0xFFFFFFFFu, v, 1);                       \
            float p0 = s_odd ? u : v;                                           \
            float p1 = s_odd ? v : u;                                           \
            uint32_t h  = pack_h2(p0, p1);                                      \
            uint32_t lo = pack_h2(p0 - h2_lo(h), p1 - h2_hi(h));                \
            if ((r >> 2) == s_odd) {                                            \
                int tok = set * 8 + r;                                          \
                Ah[AW2(s_kp, tok)] = h;                                         \
                Al[AW2(s_kp, tok)] = lo;                                        \
            }                                                                   \
        }                                                                       \
    } while (0)

    STORE_CHUNK(0);
    __syncthreads();

#pragma unroll 1
    for (int c = 0; c < NCHUNK; ++c) {
        const int buf = c & 1;
        const bool more = (c + 1 < NCHUNK);

        if (more) {
            const int cb = (c + 1) * KC;
#pragma unroll
            for (int r = 0; r < 8; ++r) {
                vx[r] = xg[(size_t)r * DIM + cb];
                vn[r] = ng[(size_t)r * DIM + cb];
            }
        }

        // ---- my k16 step: B frags from L2, A frags from smem ----
        {
            const size_t gstep = (size_t)c * 2 + set;
            const uint2* Bh = g_Bhf + gstep * 256 + lane;
            const uint2* Bl = g_Blf + gstep * 256 + lane;
            uint2 bh[8], bl[8];
#pragma unroll
            for (int j = 0; j < 8; ++j) bh[j] = __ldg(Bh + j * 32);
#pragma unroll
            for (int j = 0; j < 8; ++j) bl[j] = __ldg(Bl + j * 32);

            const uint32_t* Ah = (const uint32_t*)(db + AHIB(buf));
            const uint32_t* Al = (const uint32_t*)(db + ALOB(buf));
            const int kb = set * 8;
            uint32_t ah[4], al[4];
            ah[0] = Ah[AW2(kb + tig, g)];
            ah[1] = Ah[AW2(kb + tig, g + 8)];
            ah[2] = Ah[AW2(kb + tig + 4, g)];
            ah[3] = Ah[AW2(kb + tig + 4, g + 8)];
            al[0] = Al[AW2(kb + tig, g)];
            al[1] = Al[AW2(kb + tig, g + 8)];
            al[2] = Al[AW2(kb + tig + 4, g)];
            al[3] = Al[AW2(kb + tig + 4, g + 8)];

            // T1: a_hi * b_hi
#pragma unroll
            for (int j = 0; j < 8; ++j)
                mma_f16(acc[j], ah[0], ah[1], ah[2], ah[3], bh[j].x, bh[j].y);
            // T3: a_lo * b_hi
#pragma unroll
            for (int j = 0; j < 8; ++j)
                mma_f16(acc[j], al[0], al[1], al[2], al[3], bh[j].x, bh[j].y);
            // T2: a_hi * b_lo
#pragma unroll
            for (int j = 0; j < 8; ++j)
                mma_f16(acc[j], ah[0], ah[1], ah[2], ah[3], bl[j].x, bl[j].y);
        }

        if (more) STORE_CHUNK(buf ^ 1);
        __syncthreads();
    }

    // ---- epilogue: K-set reduction into L[16][65] (overlays staging) ----
    float* L = (float*)db;
    if (set == 0) {
#pragma unroll
        for (int j = 0; j < 8; ++j) {
            int r = g, cb = j * 8 + tig * 2;
            L[r * 65 + cb]           = acc[j][0];
            L[r * 65 + cb + 1]       = acc[j][1];
            L[(r + 8) * 65 + cb]     = acc[j][2];
            L[(r + 8) * 65 + cb + 1] = acc[j][3];
        }
    }
    __syncthreads();
    if (set == 1) {
#pragma unroll
        for (int j = 0; j < 8; ++j) {
            int r = g, cb = j * 8 + tig * 2;
            L[r * 65 + cb]           += acc[j][0];
            L[r * 65 + cb + 1]       += acc[j][1];
            L[(r + 8) * 65 + cb]     += acc[j][2];
            L[(r + 8) * 65 + cb + 1] += acc[j][3];
        }
    }
    __syncthreads();

    float* gL = out + OFF_LOGITS + (size_t)tok0 * NEXP;
    for (int idx = tid; idx < MT * NEXP; idx += THREADS)
        gL[idx] = L[(idx >> 6) * 65 + (idx & 63)];
    __syncthreads();

    if (tid < MT) {
        float* row = L + tid * 65;
        float mx = row[0];
#pragma unroll 8
        for (int e = 1; e < NEXP; ++e) mx = fmaxf(mx, row[e]);
        float s = 0.0f;
#pragma unroll 8
        for (int e = 0; e < NEXP; ++e) s += expf(row[e] - mx);
        float inv = 1.0f / s;
#pragma unroll 8
        for (int e = 0; e < NEXP; ++e) row[e] = expf(row[e] - mx) * inv;
    }
    __syncthreads();

    float* gS = out + OFF_SCORES + (size_t)tok0 * NEXP;
    for (int idx = tid; idx < MT * NEXP; idx += THREADS)
        gS[idx] = L[(idx >> 6) * 65 + (idx & 63)];

    // top-12 biased ranking; write top-8; smem counts; flag near-ties
    if (tid < MT) {
        const float* rp = L + tid * 65;
        float bv[NCAND];
        int   bix[NCAND];
        u64 mask = 0ull;
#pragma unroll
        for (int k = 0; k < NCAND; ++k) {
            float best = -1e30f;
            int bi = 0;
            for (int e = 0; e < NEXP; ++e) {
                if (!((mask >> e) & 1ull)) {
                    float v = rp[e] + s_bias[e];
                    if (v > best) { best = v; bi = e; }
                }
            }
            mask |= 1ull << bi;
            bv[k] = best;
            bix[k] = bi;
        }
        float w[TOPK], ss = 0.0f;
#pragma unroll
        for (int k = 0; k < TOPK; ++k) { w[k] = rp[bix[k]]; ss += w[k] * w[k]; }
        float winv = 1.0f / sqrtf(ss);

        const int tok = tok0 + tid;
        float* gW = out + OFF_W   + (size_t)tok * TOPK;
        float* gI = out + OFF_IDX + (size_t)tok * TOPK;
#pragma unroll
        for (int k = 0; k < TOPK; ++k) {
            gW[k] = w[k] * winv;
            gI[k] = (float)bix[k];
            atomicAdd(&s_cnt[bix[k]], 1.0f);
        }

        float ming = bv[0] - bv[1];
#pragma unroll
        for (int j = 1; j < 8; ++j) ming = fminf(ming, bv[j] - bv[j + 1]);
        if (ming < THRESH) {
            int pos = atomicAdd(&g_nflag, 1);
            g_list[pos] = tok;
#pragma unroll
            for (int j = 0; j < NCAND; ++j) g_cand[tok * NCAND + j] = bix[j];
        }
    }
    __syncthreads();

    // flush per-CTA counts (integer-valued floats: exact, order-free)
    {
        float cc = s_cnt[tid];
        if (cc != 0.0f) atomicAdd(out + OFF_CNT + tid, cc);
    }
}

// Repair: recompute 12 candidate logits in exact fp32 for flagged tokens,
// re-rank, rewrite indices + weights, and patch the expert counts by delta.
__global__ void __launch_bounds__(384, 2)
repair_kernel(const float* __restrict__ x, const float* __restrict__ sbias_g,
              const float* __restrict__ noise, float* __restrict__ out) {
    __shared__ float sxj[DIM];
    __shared__ float sl[NCAND];
    __shared__ int   se[NCAND];

    const int tid  = threadIdx.x;
    const int wid  = tid >> 5;
    const int lane = tid & 31;
    const int n    = g_nflag;

    for (int i = blockIdx.x; i < n; i += gridDim.x) {
        const int tok = g_list[i];
        __syncthreads();

        const float* xr = x     + (size_t)tok * DIM;
        const float* nr = noise + (size_t)tok * DIM;
        for (int idx = tid; idx < DIM; idx += 384)
            sxj[idx] = xr[idx] * (0.99f + nr[idx] * 0.02f);
        __syncthreads();

        if (wid < NCAND) {
            const int e = g_cand[tok * NCAND + wid];
            const float* wt = g_WT + (size_t)e * DIM;
            float a = 0.0f;
            for (int k = lane; k < DIM; k += 32 * 4) {
                a += sxj[k]       * wt[k];
                a += sxj[k + 32]  * wt[k + 32];
                a += sxj[k + 64]  * wt[k + 64];
                a += sxj[k + 96]  * wt[k + 96];
            }
#pragma unroll
            for (int o = 16; o; o >>= 1) a += __shfl_xor_sync(0xFFFFFFFFu, a, o);
            if (lane == 0) { sl[wid] = a; se[wid] = e; }
        }
        __syncthreads();

        if (tid == 0) {
            float mxl = sl[0];
#pragma unroll
            for (int j = 1; j < NCAND; ++j) mxl = fmaxf(mxl, sl[j]);
            float s0 = out[OFF_SCORES + (size_t)tok * NEXP + se[0]];
            float C = s0 / expf(sl[0] - mxl);
            float bval[NCAND];
#pragma unroll
            for (int j = 0; j < NCAND; ++j)
                bval[j] = expf(sl[j] - mxl) * C + sbias_g[se[j]];

            int ix[TOPK];
            unsigned m2 = 0;
#pragma unroll
            for (int k = 0; k < TOPK; ++k) {
                float best = -1e30f;
                int bj = 0, beste = NEXP;
                for (int j = 0; j < NCAND; ++j) {
                    if (!((m2 >> j) & 1u)) {
                        float v = bval[j];
                        int e = se[j];
                        if (v > best || (v == best && e < beste)) {
                            best = v; bj = j; beste = e;
                        }
                    }
                }
                m2 |= 1u << bj;
                ix[k] = se[bj];
            }
            float w[TOPK], ss = 0.0f;
#pragma unroll
            for (int k = 0; k < TOPK; ++k) {
                w[k] = out[OFF_SCORES + (size_t)tok * NEXP + ix[k]];
                ss += w[k] * w[k];
            }
            float winv = 1.0f / sqrtf(ss);
            float* gW = out + OFF_W   + (size_t)tok * TOPK;
            float* gI = out + OFF_IDX + (size_t)tok * TOPK;
            float* cnt = out + OFF_CNT;
#pragma unroll
            for (int k = 0; k < TOPK; ++k) {
                int oldix = (int)gI[k];
                if (oldix != ix[k]) {
                    atomicAdd(cnt + oldix, -1.0f);
                    atomicAdd(cnt + ix[k],  1.0f);
                }
                gW[k] = w[k] * winv;
                gI[k] = (float)ix[k];
            }
        }
    }
}

extern "C" void kernel_launch(void* const* d_in, const int* in_sizes, int n_in,
                              void* d_out, int out_size) {
    const float* x     = (const float*)d_in[0];
    const float* W     = (const float*)d_in[1];
    const float* sbias = (const float*)d_in[2];
    const float* noise = (const float*)d_in[3];
    float* out = (float*)d_out;

    prep_W_kernel<<<256, 256>>>(W, out + OFF_CNT);
    router_kernel<<<NBLK, THREADS, SMEM_BYTES>>>(x, sbias, noise, out);
    repair_kernel<<<256, 384>>>(x, sbias, noise, out);
}